// round 17
// baseline (speedup 1.0000x reference)
#include <cuda_runtime.h>

#define DIM 16
#define MAX_B 131072
#define K1_T 256
#define K1_SB 256                 // samples per block (1 per thread)
#define MAX_K1B (MAX_B / K1_SB)   // 512
#define K2_T 256

// ---- device scratch (no allocations allowed) ----
__device__ float4 g_q[MAX_B];            // per-sample expectation values
__device__ float  g_part[MAX_K1B * 8];   // per-block {sum q_w, sum q_w^2}
__device__ float  g_stats[8];            // scale[4], shift[4]
__device__ int    g_ctr = 0;

// ============================================================
// Pool one sample's lane-L columns straight from GLOBAL memory.
// ============================================================
template<int L>
__device__ __forceinline__ float4 pool_round(const float4* __restrict__ bp) {
    float q0 = 0.f, q1 = 0.f, q2 = 0.f, q3 = 0.f;
#pragma unroll
    for (int i = 0; i < 9; ++i) {
        const int pos = L + 4 * i;        // 0..35
        float4 v = __ldg(bp + pos);
        const int row = pos / 3;          // compile-time
        const int m3  = pos % 3;          // compile-time
        float a = v.x + v.y, b = v.z + v.w;
        if (row < 6) {
            if (m3 == 0)      { q0 += a + b; }
            else if (m3 == 1) { q0 += a; q1 += b; }
            else              { q1 += a + b; }
        } else {
            if (m3 == 0)      { q2 += a + b; }
            else if (m3 == 1) { q2 += a; q3 += b; }
            else              { q3 += a + b; }
        }
    }
    return make_float4(q0, q1, q2, q3);
}

// ============================================================
// K1: per-block parallel build_U (shfl butterflies) + pool
// (direct from gmem) + circuit + BN partials; last block folds
// partials into scale/shift and resets the counter.
// 256 threads = 256 samples per block.
// ============================================================
__global__ void __launch_bounds__(K1_T)
fused_kernel(const float* __restrict__ x, const float* __restrict__ W,
             const float* __restrict__ gamma, const float* __restrict__ beta,
             int B, float invB) {
    __shared__ float2 trigS[24];          // (cos(t/2), sin(t/2)) per gate param
    __shared__ float4 sU[DIM * 8];        // 2KB unitary
    __shared__ float  sred[8 * 8];
    __shared__ bool   sIsLast;

    const int tid  = threadIdx.x;
    const int lane = tid & 31;
    const int warp = tid >> 5;
    const long blockStart = (long)blockIdx.x * K1_SB;
    const long warpBase   = blockStart + warp * 32;
    const float4* __restrict__ x4 = (const float4*)x;

    // ---- build U in-block: 256 threads = 16 cols x 16 rows ----
    if (tid < 24) {
        float th = W[tid] * 0.5f;
        trigS[tid] = make_float2(cosf(th), sinf(th));
    }
    __syncthreads();
    {
        const int c = tid >> 4;           // column 0..15
        const int r = tid & 15;           // row 0..15
        float2 st = make_float2(r == c ? 1.f : 0.f, 0.f);

#pragma unroll
        for (int l = 0; l < 2; l++) {
#pragma unroll
            for (int w = 0; w < 4; w++) {
                const int m = 1 << (3 - w);
                const int bit = (r & m) != 0;
                const int gi = (l * 4 + w) * 3;
                // RX
                {
                    float2 tg = trigS[gi + 0];
                    float ore = __shfl_xor_sync(0xffffffffu, st.x, m);
                    float oim = __shfl_xor_sync(0xffffffffu, st.y, m);
                    st = make_float2(tg.x * st.x + tg.y * oim,
                                     tg.x * st.y - tg.y * ore);
                }
                // RY
                {
                    float2 tg = trigS[gi + 1];
                    float ore = __shfl_xor_sync(0xffffffffu, st.x, m);
                    float oim = __shfl_xor_sync(0xffffffffu, st.y, m);
                    float s = bit ? tg.y : -tg.y;
                    st = make_float2(tg.x * st.x + s * ore,
                                     tg.x * st.y + s * oim);
                }
                // RZ
                {
                    float2 tg = trigS[gi + 2];
                    float sn = bit ? tg.y : -tg.y;
                    st = make_float2(tg.x * st.x - sn * st.y,
                                     tg.x * st.y + sn * st.x);
                }
            }
            // CNOT ring
#pragma unroll
            for (int w = 0; w < 4; w++) {
                const int tw = (w + 1) & 3;
                const int cm = 1 << (3 - w), tm = 1 << (3 - tw);
                const int src = (r & cm) ? (r ^ tm) : r;
                const int srcLane = (tid & 16) | src;
                float ore = __shfl_sync(0xffffffffu, st.x, srcLane);
                float oim = __shfl_sync(0xffffffffu, st.y, srcLane);
                st = make_float2(ore, oim);
            }
        }
        // fold (-i)^popc(c), write directly into sU layout
        const int pc = __popc(c) & 3;
        float2 o;
        if (pc == 0)      o = st;
        else if (pc == 1) o = make_float2(st.y, -st.x);
        else if (pc == 2) o = make_float2(-st.x, -st.y);
        else              o = make_float2(-st.y, st.x);
        ((float2*)sU)[c * 16 + r] = o;
    }
    __syncthreads();

    // ---- pool: 4 rounds of 8 samples per warp ----
    float a0 = 0.f, a1 = 0.f, a2 = 0.f, a3 = 0.f;
#pragma unroll
    for (int r = 0; r < 4; ++r) {
        long sampleBase = warpBase + 8 * r + (lane >> 2);
        const float4* bp = x4 + (sampleBase < B ? sampleBase : 0) * 36;

        float4 acc;
        switch (lane & 3) {
            case 0:  acc = pool_round<0>(bp); break;
            case 1:  acc = pool_round<1>(bp); break;
            case 2:  acc = pool_round<2>(bp); break;
            default: acc = pool_round<3>(bp); break;
        }

#pragma unroll
        for (int off = 1; off <= 2; off <<= 1) {
            acc.x += __shfl_xor_sync(0xffffffffu, acc.x, off);
            acc.y += __shfl_xor_sync(0xffffffffu, acc.y, off);
            acc.z += __shfl_xor_sync(0xffffffffu, acc.z, off);
            acc.w += __shfl_xor_sync(0xffffffffu, acc.w, off);
        }
        float sel01 = (lane & 1) ? acc.y : acc.x;
        float sel23 = (lane & 1) ? acc.w : acc.z;
        float outv  = (lane & 2) ? sel23 : sel01;

        int srcBase = (lane & 7) << 2;
        float v0 = __shfl_sync(0xffffffffu, outv, srcBase | 0);
        float v1 = __shfl_sync(0xffffffffu, outv, srcBase | 1);
        float v2 = __shfl_sync(0xffffffffu, outv, srcBase | 2);
        float v3 = __shfl_sync(0xffffffffu, outv, srcBase | 3);
        if ((lane >> 3) == r) { a0 = v0; a1 = v1; a2 = v2; a3 = v3; }
    }

    // ---- circuit: every thread, its own sample ----
    float s0 = 0.f, s1 = 0.f, s2 = 0.f, s3 = 0.f;
    const long gi = blockStart + tid;

    if (gi < B) {
        const float h = 0.5f / 36.f;
        float c0, n0, c1, n1, c2, n2, c3, n3;
        __sincosf(a0 * h, &n0, &c0);
        __sincosf(a1 * h, &n1, &c1);
        __sincosf(a2 * h, &n2, &c2);
        __sincosf(a3 * h, &n3, &c3);

        float hi[4] = { c0 * c1, c0 * n1, n0 * c1, n0 * n1 };
        float lo[4] = { c2 * c3, c2 * n3, n2 * c3, n2 * n3 };
        float m[DIM];
#pragma unroll
        for (int c = 0; c < DIM; c++) m[c] = hi[c >> 2] * lo[c & 3];

        unsigned long long acc[DIM];
#pragma unroll
        for (int r = 0; r < DIM; r++) acc[r] = 0ull;

        const longlong2* __restrict__ sU2 = (const longlong2*)sU;
#pragma unroll
        for (int c = 0; c < DIM; c++) {
            unsigned long long mm;
            asm("mov.b64 %0, {%1, %2};" : "=l"(mm) : "f"(m[c]), "f"(m[c]));
#pragma unroll
            for (int r4 = 0; r4 < 8; r4++) {
                longlong2 u = sU2[c * 8 + r4];
                asm("fma.rn.f32x2 %0, %1, %2, %0;"
                    : "+l"(acc[2 * r4]) : "l"((unsigned long long)u.x), "l"(mm));
                asm("fma.rn.f32x2 %0, %1, %2, %0;"
                    : "+l"(acc[2 * r4 + 1]) : "l"((unsigned long long)u.y), "l"(mm));
            }
        }

        float p[DIM];
#pragma unroll
        for (int r = 0; r < DIM; r++) {
            float re, im;
            asm("mov.b64 {%0, %1}, %2;" : "=f"(re), "=f"(im) : "l"(acc[r]));
            p[r] = re * re + im * im;
        }

        float e1[8];
#pragma unroll
        for (int j = 0; j < 8; j++) { e1[j] = p[2 * j] + p[2 * j + 1]; s3 += p[2 * j] - p[2 * j + 1]; }
        float e2[4];
#pragma unroll
        for (int j = 0; j < 4; j++) { e2[j] = e1[2 * j] + e1[2 * j + 1]; s2 += e1[2 * j] - e1[2 * j + 1]; }
        float e3[2];
#pragma unroll
        for (int j = 0; j < 2; j++) { e3[j] = e2[2 * j] + e2[2 * j + 1]; s1 += e2[2 * j] - e2[2 * j + 1]; }
        s0 = e3[0] - e3[1];

        g_q[gi] = make_float4(s0, s1, s2, s3);
    }

    // ---- BN partial sums: all 8 warps ----
    float u0 = s0 * s0, u1 = s1 * s1, u2 = s2 * s2, u3 = s3 * s3;
#pragma unroll
    for (int off = 16; off >= 1; off >>= 1) {
        s0 += __shfl_xor_sync(0xffffffffu, s0, off);
        s1 += __shfl_xor_sync(0xffffffffu, s1, off);
        s2 += __shfl_xor_sync(0xffffffffu, s2, off);
        s3 += __shfl_xor_sync(0xffffffffu, s3, off);
        u0 += __shfl_xor_sync(0xffffffffu, u0, off);
        u1 += __shfl_xor_sync(0xffffffffu, u1, off);
        u2 += __shfl_xor_sync(0xffffffffu, u2, off);
        u3 += __shfl_xor_sync(0xffffffffu, u3, off);
    }
    if (lane == 0) {
        sred[warp * 8 + 0] = s0; sred[warp * 8 + 1] = s1;
        sred[warp * 8 + 2] = s2; sred[warp * 8 + 3] = s3;
        sred[warp * 8 + 4] = u0; sred[warp * 8 + 5] = u1;
        sred[warp * 8 + 6] = u2; sred[warp * 8 + 7] = u3;
    }
    __syncthreads();
    if (tid < 8) {
        float a8 = 0.f;
#pragma unroll
        for (int w = 0; w < 8; w++) a8 += sred[w * 8 + tid];
        g_part[blockIdx.x * 8 + tid] = a8;
    }
    __threadfence();
    __syncthreads();
    if (tid == 0) {
        int prev = atomicAdd(&g_ctr, 1);
        sIsLast = (prev == (int)gridDim.x - 1);
    }
    __syncthreads();

    // ---- last block: reduce partials -> scale/shift; reset ctr ----
    if (sIsLast) {
        __threadfence();   // acquire: see all g_part writes
        const int nPart = (int)gridDim.x * 8;
        float acc = 0.f;
        for (int j = tid; j < nPart; j += K1_T) acc += g_part[j];  // component = tid % 8
        acc += __shfl_xor_sync(0xffffffffu, acc, 8);
        acc += __shfl_xor_sync(0xffffffffu, acc, 16);
        if (lane < 8) sred[warp * 8 + lane] = acc;
        __syncthreads();
        if (tid < 8) {
            float a8 = 0.f;
#pragma unroll
            for (int w = 0; w < 8; ++w) a8 += sred[w * 8 + tid];
            sred[32 + tid] = a8;
        }
        __syncthreads();
        if (tid < 4) {
            float mean  = sred[32 + tid] * invB;
            float var   = sred[36 + tid] * invB - mean * mean;
            float scale = rsqrtf(var + 1e-5f) * gamma[tid];
            g_stats[tid]     = scale;
            g_stats[tid + 4] = beta[tid] - mean * scale;
        }
        if (tid == 0) g_ctr = 0;   // reset for next graph replay (we are the last block)
    }
}

// ============================================================
// K2: pure streaming normalize  out = q*scale + shift
// ============================================================
__global__ void __launch_bounds__(K2_T)
norm_kernel(float* __restrict__ out, int B) {
    const int tid = threadIdx.x;
    long i = (long)blockIdx.x * K2_T + tid;
    float sc0 = g_stats[0], sc1 = g_stats[1], sc2 = g_stats[2], sc3 = g_stats[3];
    float sh0 = g_stats[4], sh1 = g_stats[5], sh2 = g_stats[6], sh3 = g_stats[7];
    if (i < B) {
        float4 q = g_q[i];
        float4 o;
        o.x = q.x * sc0 + sh0;
        o.y = q.y * sc1 + sh1;
        o.z = q.z * sc2 + sh2;
        o.w = q.w * sc3 + sh3;
        ((float4*)out)[i] = o;
    }
}

// ============================================================
extern "C" void kernel_launch(void* const* d_in, const int* in_sizes, int n_in,
                              void* d_out, int out_size) {
    const float* x     = (const float*)d_in[0];
    const float* W     = (const float*)d_in[1];
    const float* gamma = (const float*)d_in[2];
    const float* beta  = (const float*)d_in[3];
    float* out = (float*)d_out;

    int B = in_sizes[0] / 144;
    if (B > MAX_B) B = MAX_B;

    int g1 = (B + K1_SB - 1) / K1_SB;
    fused_kernel<<<g1, K1_T>>>(x, W, gamma, beta, B, 1.0f / (float)B);
    int g2 = (B + K2_T - 1) / K2_T;
    norm_kernel<<<g2, K2_T>>>(out, B);
}